// round 5
// baseline (speedup 1.0000x reference)
#include <cuda_runtime.h>
#include <cstdint>

// ---------------- problem constants ----------------
#define BB 8
#define TT 256
#define UU 64
#define JJ 512          // K dim
#define VV 300          // vocab
#define NP 320          // padded vocab (mult of 8)
#define NCHUNK 16       // K chunks of 32
#define CHUNK_FLOATS 10240   // B frag floats per chunk: 40 nt * 4 ks * 64

// ---------------- scratch (device globals; no allocs allowed) ----------------
__device__ float g_enc_s[BB * TT * JJ];                 // 4 MB   (enc projection)
__device__ float g_pred_s[BB * UU * JJ];                // 1 MB   (pred projection)
__device__ float g_wfrag[NCHUNK * CHUNK_FLOATS];        // 640 KB (W_out, tf32, fragment-ready, ks-paired)

// ---------------- helpers ----------------
__device__ __forceinline__ uint32_t f2tf32(float x) {
    uint32_t r;
    asm("cvt.rna.tf32.f32 %0, %1;" : "=r"(r) : "f"(x));
    return r;
}

// hardware tanh: single MUFU op
__device__ __forceinline__ float tanh_ap(float x) {
    float y;
    asm("tanh.approx.f32 %0, %1;" : "=f"(y) : "f"(x));
    return y;
}

__device__ __forceinline__ void mma_tf32(float* d, const uint32_t* a, uint32_t b0, uint32_t b1) {
    asm volatile(
        "mma.sync.aligned.m16n8k8.row.col.f32.tf32.tf32.f32 "
        "{%0,%1,%2,%3}, {%4,%5,%6,%7}, {%8,%9}, {%0,%1,%2,%3};"
        : "+f"(d[0]), "+f"(d[1]), "+f"(d[2]), "+f"(d[3])
        : "r"(a[0]), "r"(a[1]), "r"(a[2]), "r"(a[3]), "r"(b0), "r"(b1));
}

// ---------------- kernel 1: W_out -> tf32 fragment-ready, ks-paired layout ----------------
// Byte layout within a chunk: nt*1024 + (ks>>1)*512 + lane*16 + (ks&1)*8 + h*4
// Fragment value: b_h = W[n = nt*8 + lane/4][k = c*32 + ks*8 + lane%4 + 4h]  (0 if n >= 300)
__global__ void prep_wfrag_kernel(const float* __restrict__ W_out) {
    const int idx = blockIdx.x * 256 + threadIdx.x;     // covers 16 * 10240 exactly
    const int c   = idx / CHUNK_FLOATS;
    const int rem = idx - c * CHUNK_FLOATS;
    const int nt  = rem >> 8;
    const int r2  = rem & 255;
    const int ks2 = r2 >> 7;
    const int r3  = r2 & 127;
    const int lane = r3 >> 2;
    const int ksodd = (r3 >> 1) & 1;
    const int h   = r3 & 1;
    const int ks  = ks2 * 2 + ksodd;
    const int n   = nt * 8 + (lane >> 2);
    const int k   = c * 32 + ks * 8 + (lane & 3) + 4 * h;
    float val = (n < VV) ? W_out[n * JJ + k] : 0.0f;
    g_wfrag[idx] = __uint_as_float(f2tf32(val));
}

// ---------------- kernel 2: enc/pred projections (fp32 FFMA tiled GEMM) ----------------
__global__ __launch_bounds__(256) void proj_kernel(
    const float* __restrict__ enc, const float* __restrict__ pred,
    const float* __restrict__ W_enc, const float* __restrict__ b_enc,
    const float* __restrict__ W_pred, const float* __restrict__ b_pred)
{
    __shared__ __align__(16) float As[16][68];
    __shared__ __align__(16) float Bs[16][68];

    const int z = blockIdx.z;
    const int bx = blockIdx.x, by = blockIdx.y;
    if (z == 1 && bx >= 8) return;

    const float* X    = z ? pred     : enc;
    const float* W    = z ? W_pred   : W_enc;
    const float* bias = z ? b_pred   : b_enc;
    float*       Y    = z ? g_pred_s : g_enc_s;

    const int tid = threadIdx.x;
    const int m0 = bx * 64, n0 = by * 64;
    const int r  = tid >> 2, qq = tid & 3;
    const int tx = tid & 15, ty = tid >> 4;

    float acc[4][4] = {};

    for (int k0 = 0; k0 < JJ; k0 += 16) {
        float4 a4 = *(const float4*)(X + (size_t)(m0 + r) * JJ + k0 + qq * 4);
        float4 w4 = *(const float4*)(W + (size_t)(n0 + r) * JJ + k0 + qq * 4);
        __syncthreads();
        As[qq * 4 + 0][r] = a4.x; As[qq * 4 + 1][r] = a4.y;
        As[qq * 4 + 2][r] = a4.z; As[qq * 4 + 3][r] = a4.w;
        Bs[qq * 4 + 0][r] = w4.x; Bs[qq * 4 + 1][r] = w4.y;
        Bs[qq * 4 + 2][r] = w4.z; Bs[qq * 4 + 3][r] = w4.w;
        __syncthreads();
        #pragma unroll
        for (int d = 0; d < 16; d++) {
            float4 av = *(const float4*)&As[d][ty * 4];
            float4 bv = *(const float4*)&Bs[d][tx * 4];
            float a[4]  = {av.x, av.y, av.z, av.w};
            float bb[4] = {bv.x, bv.y, bv.z, bv.w};
            #pragma unroll
            for (int i = 0; i < 4; i++)
                #pragma unroll
                for (int j = 0; j < 4; j++)
                    acc[i][j] += a[i] * bb[j];
        }
    }

    float4 bia = *(const float4*)(bias + n0 + tx * 4);
    float bb[4] = {bia.x, bia.y, bia.z, bia.w};
    #pragma unroll
    for (int i = 0; i < 4; i++) {
        float4 o;
        o.x = acc[i][0] + bb[0]; o.y = acc[i][1] + bb[1];
        o.z = acc[i][2] + bb[2]; o.w = acc[i][3] + bb[3];
        *(float4*)(Y + (size_t)(m0 + ty * 4 + i) * JJ + n0 + tx * 4) = o;
    }
}

// ---------------- kernel 3: fused tanh-joint + vocab GEMM (mma.sync tf32) ----------------
// Grid: 1024 CTAs = (b, t-pair). CTA tile: M=128 (2t x 64u) x N=320(pad) x K=512.
// 512 threads = 16 warps, warp grid 4Mx4N, warp tile 32x80.
static constexpr int OFF_BIAS = 0;
static constexpr int OFF_A    = 2048;
static constexpr int A_STRIDE = 16384;                 // 32 frags x 512B
static constexpr int OFF_B    = 2048 + 2 * 16384;      // 34816
static constexpr int B_STRIDE = 40960;                 // 40 nt x 1024B
static constexpr int JK_SMEM  = OFF_B + 2 * B_STRIDE;  // 116736 -> 1 CTA/SM

__global__ __launch_bounds__(512, 1) void joint_kernel(const float* __restrict__ b_out,
                                                       float* __restrict__ out)
{
    extern __shared__ char smem[];
    const int tid  = threadIdx.x;
    const int wid  = tid >> 5;
    const int lane = tid & 31;
    const int b    = blockIdx.x >> 7;
    const int t0   = (blockIdx.x & 127) * 2;

    const int warp_m = wid >> 2;      // 0..3 -> rows  warp_m*32 .. +32
    const int warp_n = wid & 3;       // 0..3 -> cols  warp_n*80 .. +80
    const int ntbase = warp_n * 10;
    const int mt0 = warp_m * 2, mt1 = warp_m * 2 + 1;

    float* bias_sm = (float*)(smem + OFF_BIAS);
    for (int i = tid; i < NP; i += 512) bias_sm[i] = (i < VV) ? b_out[i] : 0.0f;

    const float* __restrict__ encR0 = g_enc_s + (size_t)(b * TT + t0) * JJ;
    const float* __restrict__ predB = g_pred_s + (size_t)b * UU * JJ;

    float acc[2][10][4];
    #pragma unroll
    for (int i = 0; i < 2; i++)
        #pragma unroll
        for (int j = 0; j < 10; j++)
            #pragma unroll
            for (int k = 0; k < 4; k++) acc[i][j][k] = 0.0f;

    // A producer: thread handles quads qi = tid, tid+512.
    //   m = qi & 127 (row), qp = qi >> 7 (k-quad 0..7). Loads 2x LDG.128, 4x tanh, 4x STS.32.
    //   Dest frag: mt=m>>4, ks=qp>>1, f=mt*4+ks; r=m&7, half_m=(m>>3)&1, half_k=qp&1;
    //   value j goes to lane r*4+j, reg half_m+2*half_k.
    #define PRODUCE(cc, bufp)  do {                                                   \
        const int k0p = (cc) * 32;                                                    \
        char* Abuf = smem + OFF_A + (bufp) * A_STRIDE;                                \
        _Pragma("unroll")                                                             \
        for (int ii = 0; ii < 2; ii++) {                                              \
            const int qi = tid + ii * 512;                                            \
            const int m = qi & 127, qp = qi >> 7;                                     \
            const int tl = m >> 6, u = m & 63;                                        \
            const float4 e = *(const float4*)(encR0 + (size_t)tl * JJ + k0p + qp * 4);\
            const float4 p = *(const float4*)(predB + (size_t)u * JJ + k0p + qp * 4); \
            const int f = (m >> 4) * 4 + (qp >> 1);                                   \
            const uint32_t base = (uint32_t)(f * 512 + (m & 7) * 64                   \
                                  + (((m >> 3) & 1) + 2 * (qp & 1)) * 4);             \
            *(uint32_t*)(Abuf + base +  0) = f2tf32(tanh_ap(e.x + p.x));              \
            *(uint32_t*)(Abuf + base + 16) = f2tf32(tanh_ap(e.y + p.y));              \
            *(uint32_t*)(Abuf + base + 32) = f2tf32(tanh_ap(e.z + p.z));              \
            *(uint32_t*)(Abuf + base + 48) = f2tf32(tanh_ap(e.w + p.w));              \
        }                                                                             \
        const float4* wsrc = (const float4*)(g_wfrag + (size_t)(cc) * CHUNK_FLOATS);  \
        float4* wdst = (float4*)(smem + OFF_B + (bufp) * B_STRIDE);                   \
        _Pragma("unroll")                                                             \
        for (int ii = 0; ii < 5; ii++) wdst[tid + ii * 512] = wsrc[tid + ii * 512];   \
    } while (0)

    PRODUCE(0, 0);
    __syncthreads();

    #pragma unroll 1
    for (int c = 0; c < NCHUNK; c++) {
        const int buf = c & 1;
        if (c + 1 < NCHUNK) { PRODUCE(c + 1, buf ^ 1); }

        const char* Abuf = smem + OFF_A + buf * A_STRIDE;
        const char* Bbuf = smem + OFF_B + buf * B_STRIDE;
        #pragma unroll
        for (int ks2 = 0; ks2 < 2; ks2++) {
            // A frags for ks = 2*ks2, 2*ks2+1, both mt rows
            uint4 a00 = *(const uint4*)(Abuf + (mt0 * 4 + 2 * ks2 + 0) * 512 + lane * 16);
            uint4 a01 = *(const uint4*)(Abuf + (mt0 * 4 + 2 * ks2 + 1) * 512 + lane * 16);
            uint4 a10 = *(const uint4*)(Abuf + (mt1 * 4 + 2 * ks2 + 0) * 512 + lane * 16);
            uint4 a11 = *(const uint4*)(Abuf + (mt1 * 4 + 2 * ks2 + 1) * 512 + lane * 16);
            const uint32_t A00[4] = {a00.x, a00.y, a00.z, a00.w};
            const uint32_t A01[4] = {a01.x, a01.y, a01.z, a01.w};
            const uint32_t A10[4] = {a10.x, a10.y, a10.z, a10.w};
            const uint32_t A11[4] = {a11.x, a11.y, a11.z, a11.w};
            #pragma unroll
            for (int nt = 0; nt < 10; nt++) {
                uint4 bf = *(const uint4*)(Bbuf + (ntbase + nt) * 1024 + ks2 * 512 + lane * 16);
                mma_tf32(acc[0][nt], A00, bf.x, bf.y);
                mma_tf32(acc[1][nt], A10, bf.x, bf.y);
                mma_tf32(acc[0][nt], A01, bf.z, bf.w);
                mma_tf32(acc[1][nt], A11, bf.z, bf.w);
            }
        }
        __syncthreads();
    }

    // -------- epilogue: bias add + guarded float2 stores --------
    {
        const int rr = lane >> 2, qf = lane & 3;
        #pragma unroll
        for (int i = 0; i < 2; i++) {
            const int mbase = warp_m * 32 + i * 16 + rr;
            #pragma unroll
            for (int half = 0; half < 2; half++) {
                const int m = mbase + half * 8;
                const int tl = m >> 6, u = m & 63;
                float* orow = out + (size_t)((b * TT + t0 + tl) * UU + u) * VV;
                #pragma unroll
                for (int nt = 0; nt < 10; nt++) {
                    const int n0 = warp_n * 80 + nt * 8 + 2 * qf;
                    if (n0 < VV) {
                        float2 o;
                        o.x = acc[i][nt][half * 2 + 0] + bias_sm[n0];
                        o.y = acc[i][nt][half * 2 + 1] + bias_sm[n0 + 1];
                        *(float2*)(orow + n0) = o;
                    }
                }
            }
        }
    }
    #undef PRODUCE
}

// ---------------- launch ----------------
extern "C" void kernel_launch(void* const* d_in, const int* in_sizes, int n_in,
                              void* d_out, int out_size) {
    const float* enc    = (const float*)d_in[0];
    const float* pred   = (const float*)d_in[1];
    const float* W_enc  = (const float*)d_in[2];
    const float* b_enc  = (const float*)d_in[3];
    const float* W_pred = (const float*)d_in[4];
    const float* b_pred = (const float*)d_in[5];
    const float* W_out  = (const float*)d_in[6];
    const float* b_out  = (const float*)d_in[7];
    float* out = (float*)d_out;

    cudaFuncSetAttribute(joint_kernel, cudaFuncAttributeMaxDynamicSharedMemorySize, JK_SMEM);

    prep_wfrag_kernel<<<(NCHUNK * CHUNK_FLOATS) / 256, 256>>>(W_out);
    proj_kernel<<<dim3(32, 8, 2), 256>>>(enc, pred, W_enc, b_enc, W_pred, b_pred);
    joint_kernel<<<BB * (TT / 2), 512, JK_SMEM>>>(b_out, out);
}

// round 6
// speedup vs baseline: 1.6096x; 1.6096x over previous
#include <cuda_runtime.h>
#include <cuda_fp16.h>
#include <cstdint>

// ---------------- problem constants ----------------
#define BB 8
#define TT 256
#define UU 64
#define JJ 512          // K dim
#define VV 300          // vocab
#define NP 320          // padded vocab (mult of 8)
#define NCHUNK 16       // K chunks of 32
#define BFRAG_U32 5120  // B frag uint32 per chunk: 40 nt * 32 lanes * 4 (2 ks x 2 regs)

// ---------------- scratch (device globals; no allocs allowed) ----------------
__device__ float    g_enc_s[BB * TT * JJ];            // 4 MB   (enc projection)
__device__ float    g_pred_s[BB * UU * JJ];           // 1 MB   (pred projection)
__device__ uint32_t g_wfrag[NCHUNK * BFRAG_U32];      // 320 KB (W_out fp16, fragment-ready, ks-paired)

// ---------------- helpers ----------------
// hardware tanh: single MUFU op
__device__ __forceinline__ float tanh_ap(float x) {
    float y;
    asm("tanh.approx.f32 %0, %1;" : "=f"(y) : "f"(x));
    return y;
}

__device__ __forceinline__ uint32_t pack_h2(float lo, float hi) {
    half2 h = __floats2half2_rn(lo, hi);   // x = lo (lower half), y = hi (upper)
    return *(uint32_t*)&h;
}

__device__ __forceinline__ void mma_f16(float* d, const uint32_t* a, uint32_t b0, uint32_t b1) {
    asm volatile(
        "mma.sync.aligned.m16n8k16.row.col.f32.f16.f16.f32 "
        "{%0,%1,%2,%3}, {%4,%5,%6,%7}, {%8,%9}, {%0,%1,%2,%3};"
        : "+f"(d[0]), "+f"(d[1]), "+f"(d[2]), "+f"(d[3])
        : "r"(a[0]), "r"(a[1]), "r"(a[2]), "r"(a[3]), "r"(b0), "r"(b1));
}

// ---------------- kernel 1: W_out -> fp16 fragment-ready, ks-paired layout ----------------
// Per chunk (k=32 = 2 ksteps of 16): byte layout nt*512 + lane*16 + ks*8 + reg*4.
// reg value (half2): lo = W[n][k], hi = W[n][k+1]; n = nt*8 + lane/4, k = c*32 + ks*16 + (lane%4)*2 + reg*8.
__global__ void prep_wfrag_kernel(const float* __restrict__ W_out) {
    const int idx = blockIdx.x * 256 + threadIdx.x;     // covers 16 * 5120 = 81920 exactly
    const int c   = idx / BFRAG_U32;
    const int rem = idx - c * BFRAG_U32;
    const int nt  = rem >> 7;
    const int r2  = rem & 127;
    const int lane = r2 >> 2;
    const int sub  = r2 & 3;
    const int ks = sub >> 1, reg = sub & 1;
    const int n = nt * 8 + (lane >> 2);
    const int k = c * 32 + ks * 16 + (lane & 3) * 2 + reg * 8;
    float lo = 0.0f, hi = 0.0f;
    if (n < VV) {
        float2 w = *(const float2*)(W_out + (size_t)n * JJ + k);
        lo = w.x; hi = w.y;
    }
    g_wfrag[idx] = pack_h2(lo, hi);
}

// ---------------- kernel 2: enc/pred projections (fp32 FFMA tiled GEMM) ----------------
__global__ __launch_bounds__(256) void proj_kernel(
    const float* __restrict__ enc, const float* __restrict__ pred,
    const float* __restrict__ W_enc, const float* __restrict__ b_enc,
    const float* __restrict__ W_pred, const float* __restrict__ b_pred)
{
    __shared__ __align__(16) float As[16][68];
    __shared__ __align__(16) float Bs[16][68];

    const int z = blockIdx.z;
    const int bx = blockIdx.x, by = blockIdx.y;
    if (z == 1 && bx >= 8) return;

    const float* X    = z ? pred     : enc;
    const float* W    = z ? W_pred   : W_enc;
    const float* bias = z ? b_pred   : b_enc;
    float*       Y    = z ? g_pred_s : g_enc_s;

    const int tid = threadIdx.x;
    const int m0 = bx * 64, n0 = by * 64;
    const int r  = tid >> 2, qq = tid & 3;
    const int tx = tid & 15, ty = tid >> 4;

    float acc[4][4] = {};

    for (int k0 = 0; k0 < JJ; k0 += 16) {
        float4 a4 = *(const float4*)(X + (size_t)(m0 + r) * JJ + k0 + qq * 4);
        float4 w4 = *(const float4*)(W + (size_t)(n0 + r) * JJ + k0 + qq * 4);
        __syncthreads();
        As[qq * 4 + 0][r] = a4.x; As[qq * 4 + 1][r] = a4.y;
        As[qq * 4 + 2][r] = a4.z; As[qq * 4 + 3][r] = a4.w;
        Bs[qq * 4 + 0][r] = w4.x; Bs[qq * 4 + 1][r] = w4.y;
        Bs[qq * 4 + 2][r] = w4.z; Bs[qq * 4 + 3][r] = w4.w;
        __syncthreads();
        #pragma unroll
        for (int d = 0; d < 16; d++) {
            float4 av = *(const float4*)&As[d][ty * 4];
            float4 bv = *(const float4*)&Bs[d][tx * 4];
            float a[4]  = {av.x, av.y, av.z, av.w};
            float bb[4] = {bv.x, bv.y, bv.z, bv.w};
            #pragma unroll
            for (int i = 0; i < 4; i++)
                #pragma unroll
                for (int j = 0; j < 4; j++)
                    acc[i][j] += a[i] * bb[j];
        }
    }

    float4 bia = *(const float4*)(bias + n0 + tx * 4);
    float bb[4] = {bia.x, bia.y, bia.z, bia.w};
    #pragma unroll
    for (int i = 0; i < 4; i++) {
        float4 o;
        o.x = acc[i][0] + bb[0]; o.y = acc[i][1] + bb[1];
        o.z = acc[i][2] + bb[2]; o.w = acc[i][3] + bb[3];
        *(float4*)(Y + (size_t)(m0 + ty * 4 + i) * JJ + n0 + tx * 4) = o;
    }
}

// ---------------- kernel 3: fused tanh-joint + vocab GEMM (mma.sync fp16, fp32 accum) ----------------
// Grid: 1024 CTAs = (b, t-pair). CTA tile: M=128 (2t x 64u) x N=320(pad) x K=512.
// 512 threads = 16 warps, warp grid 4Mx4N, warp tile 32x80. K chunk 32 = 2 ksteps of 16.
// A stage: 16 frags (8 mt x 2 ks) x 512B = 8KB.  B stage: 40 nt x 512B = 20KB.
static constexpr int OFF_BIAS = 0;
static constexpr int OFF_A    = 2048;
static constexpr int A_STRIDE = 8192;
static constexpr int OFF_B    = 2048 + 2 * 8192;       // 18432
static constexpr int B_STRIDE = 20480;
static constexpr int JK_SMEM  = OFF_B + 2 * B_STRIDE;  // 59392

__global__ __launch_bounds__(512, 1) void joint_kernel(const float* __restrict__ b_out,
                                                       float* __restrict__ out)
{
    extern __shared__ char smem[];
    const int tid  = threadIdx.x;
    const int wid  = tid >> 5;
    const int lane = tid & 31;
    const int b    = blockIdx.x >> 7;
    const int t0   = (blockIdx.x & 127) * 2;

    const int warp_m = wid >> 2;      // 0..3 -> rows  warp_m*32 .. +32
    const int warp_n = wid & 3;       // 0..3 -> cols  warp_n*80 .. +80
    const int ntbase = warp_n * 10;
    const int mt0 = warp_m * 2, mt1 = warp_m * 2 + 1;   // 16-row tiles (of 8)

    float* bias_sm = (float*)(smem + OFF_BIAS);
    for (int i = tid; i < NP; i += 512) bias_sm[i] = (i < VV) ? b_out[i] : 0.0f;

    const float* __restrict__ encR0 = g_enc_s + (size_t)(b * TT + t0) * JJ;
    const float* __restrict__ predB = g_pred_s + (size_t)b * UU * JJ;

    float acc[2][10][4];
    #pragma unroll
    for (int i = 0; i < 2; i++)
        #pragma unroll
        for (int j = 0; j < 10; j++)
            #pragma unroll
            for (int k = 0; k < 4; k++) acc[i][j][k] = 0.0f;

    // A producer: one frag-lane per thread (16 frags x 32 lanes = 512).
    //   f = tid>>5 = mt*2+ks, lf = tid&31, r = lf>>2, q = lf&3.
    //   rows m0 = mt*16+r, m1 = m0+8 (same tl, u1 = u0+8); cols c0 = k0+ks*16+2q (+1), c8 = c0+8 (+1).
    //   regs: r0={A[m0][c0],A[m0][c0+1]}  r1={A[m1][c0],..}  r2={A[m0][c8],..}  r3={A[m1][c8],..}
    //   6 aligned LDG.64, 8 tanh, 4 cvt-pack, 1 conflict-free STS.128.
    #define PRODUCE(cc, bufp)  do {                                                   \
        const int k0p = (cc) * 32;                                                    \
        char* Abuf = smem + OFF_A + (bufp) * A_STRIDE;                                \
        {                                                                             \
            const int f = tid >> 5, lf = tid & 31;                                    \
            const int mt = f >> 1, ks = f & 1;                                        \
            const int rr = lf >> 2, qf = lf & 3;                                      \
            const int m0r = mt * 16 + rr;                                             \
            const int tl = m0r >> 6, u0 = m0r & 63, u1 = (m0r & 63) + 8;              \
            const int c0 = k0p + ks * 16 + qf * 2, c8 = c0 + 8;                       \
            const float* eR  = encR0 + (size_t)tl * JJ;                               \
            const float* pR0 = predB + (size_t)u0 * JJ;                               \
            const float* pR1 = predB + (size_t)u1 * JJ;                               \
            const float2 ea  = *(const float2*)(eR + c0);                             \
            const float2 eb  = *(const float2*)(eR + c8);                             \
            const float2 p0a = *(const float2*)(pR0 + c0);                            \
            const float2 p0b = *(const float2*)(pR0 + c8);                            \
            const float2 p1a = *(const float2*)(pR1 + c0);                            \
            const float2 p1b = *(const float2*)(pR1 + c8);                            \
            uint4 fr;                                                                 \
            fr.x = pack_h2(tanh_ap(ea.x + p0a.x), tanh_ap(ea.y + p0a.y));             \
            fr.y = pack_h2(tanh_ap(ea.x + p1a.x), tanh_ap(ea.y + p1a.y));             \
            fr.z = pack_h2(tanh_ap(eb.x + p0b.x), tanh_ap(eb.y + p0b.y));             \
            fr.w = pack_h2(tanh_ap(eb.x + p1b.x), tanh_ap(eb.y + p1b.y));             \
            *(uint4*)(Abuf + f * 512 + lf * 16) = fr;                                 \
        }                                                                             \
        const uint4* wsrc = (const uint4*)(g_wfrag + (size_t)(cc) * BFRAG_U32);       \
        uint4* wdst = (uint4*)(smem + OFF_B + (bufp) * B_STRIDE);                     \
        _Pragma("unroll")                                                             \
        for (int ii = 0; ii < 3; ii++) {                                              \
            const int w = tid + ii * 512;                                             \
            if (w < 1280) wdst[w] = wsrc[w];                                          \
        }                                                                             \
    } while (0)

    PRODUCE(0, 0);
    __syncthreads();

    #pragma unroll 1
    for (int c = 0; c < NCHUNK; c++) {
        const int buf = c & 1;
        if (c + 1 < NCHUNK) { PRODUCE(c + 1, buf ^ 1); }

        const char* Abuf = smem + OFF_A + buf * A_STRIDE;
        const char* Bbuf = smem + OFF_B + buf * B_STRIDE;

        const uint4 a00 = *(const uint4*)(Abuf + (mt0 * 2 + 0) * 512 + lane * 16);
        const uint4 a01 = *(const uint4*)(Abuf + (mt0 * 2 + 1) * 512 + lane * 16);
        const uint4 a10 = *(const uint4*)(Abuf + (mt1 * 2 + 0) * 512 + lane * 16);
        const uint4 a11 = *(const uint4*)(Abuf + (mt1 * 2 + 1) * 512 + lane * 16);
        const uint32_t A00[4] = {a00.x, a00.y, a00.z, a00.w};
        const uint32_t A01[4] = {a01.x, a01.y, a01.z, a01.w};
        const uint32_t A10[4] = {a10.x, a10.y, a10.z, a10.w};
        const uint32_t A11[4] = {a11.x, a11.y, a11.z, a11.w};

        #pragma unroll
        for (int nt = 0; nt < 10; nt++) {
            const uint4 bq = *(const uint4*)(Bbuf + (ntbase + nt) * 512 + lane * 16);
            mma_f16(acc[0][nt], A00, bq.x, bq.y);   // kstep 0
            mma_f16(acc[1][nt], A10, bq.x, bq.y);
            mma_f16(acc[0][nt], A01, bq.z, bq.w);   // kstep 1
            mma_f16(acc[1][nt], A11, bq.z, bq.w);
        }
        __syncthreads();
    }

    // -------- epilogue: bias add + guarded float2 stores --------
    {
        const int rr = lane >> 2, qf = lane & 3;
        #pragma unroll
        for (int i = 0; i < 2; i++) {
            const int mbase = warp_m * 32 + i * 16 + rr;
            #pragma unroll
            for (int half = 0; half < 2; half++) {
                const int m = mbase + half * 8;
                const int tl = m >> 6, u = m & 63;
                float* orow = out + (size_t)((b * TT + t0 + tl) * UU + u) * VV;
                #pragma unroll
                for (int nt = 0; nt < 10; nt++) {
                    const int n0 = warp_n * 80 + nt * 8 + 2 * qf;
                    if (n0 < VV) {
                        float2 o;
                        o.x = acc[i][nt][half * 2 + 0] + bias_sm[n0];
                        o.y = acc[i][nt][half * 2 + 1] + bias_sm[n0 + 1];
                        *(float2*)(orow + n0) = o;
                    }
                }
            }
        }
    }
    #undef PRODUCE
}

// ---------------- launch ----------------
extern "C" void kernel_launch(void* const* d_in, const int* in_sizes, int n_in,
                              void* d_out, int out_size) {
    const float* enc    = (const float*)d_in[0];
    const float* pred   = (const float*)d_in[1];
    const float* W_enc  = (const float*)d_in[2];
    const float* b_enc  = (const float*)d_in[3];
    const float* W_pred = (const float*)d_in[4];
    const float* b_pred = (const float*)d_in[5];
    const float* W_out  = (const float*)d_in[6];
    const float* b_out  = (const float*)d_in[7];
    float* out = (float*)d_out;

    cudaFuncSetAttribute(joint_kernel, cudaFuncAttributeMaxDynamicSharedMemorySize, JK_SMEM);

    prep_wfrag_kernel<<<(NCHUNK * BFRAG_U32) / 256, 256>>>(W_out);
    proj_kernel<<<dim3(32, 8, 2), 256>>>(enc, pred, W_enc, b_enc, W_pred, b_pred);
    joint_kernel<<<BB * (TT / 2), 512, JK_SMEM>>>(b_out, out);
}

// round 7
// speedup vs baseline: 2.3643x; 1.4689x over previous
#include <cuda_runtime.h>
#include <cuda_fp16.h>
#include <cstdint>

// ---------------- problem constants ----------------
#define BB 8
#define TT 256
#define UU 64
#define JJ 512          // K dim
#define VV 300          // vocab
#define NP 320          // padded vocab (mult of 8)
#define NCHUNK 16       // K chunks of 32
#define BFRAG_U32 5120  // joint B frag u32 per chunk: 40 nt * 32 lanes * 4

// ---------------- scratch (device globals; no allocs allowed) ----------------
__device__ __align__(16) float    g_enc_s[BB * TT * JJ];        // 4 MB   (enc projection out)
__device__ __align__(16) float    g_pred_s[BB * UU * JJ];       // 1 MB   (pred projection out)
__device__ __align__(16) uint32_t g_wfrag[NCHUNK * BFRAG_U32];  // 320 KB (W_out fp16 frags)
__device__ __align__(16) uint32_t g_wef[NCHUNK * 64 * 128];     // 512 KB (W_enc fp16 frags)
__device__ __align__(16) uint32_t g_wpf[NCHUNK * 64 * 128];     // 512 KB (W_pred fp16 frags)

// ---------------- helpers ----------------
__device__ __forceinline__ uint32_t smem_u32(const void* p) {
    uint32_t a;
    asm("{ .reg .u64 t; cvta.to.shared.u64 t, %1; cvt.u32.u64 %0, t; }" : "=r"(a) : "l"(p));
    return a;
}

__device__ __forceinline__ float tanh_ap(float x) {
    float y;
    asm("tanh.approx.f32 %0, %1;" : "=f"(y) : "f"(x));
    return y;
}

__device__ __forceinline__ uint32_t pack_h2(float lo, float hi) {
    half2 h = __floats2half2_rn(lo, hi);
    return *(uint32_t*)&h;
}

__device__ __forceinline__ void cp_async16(uint32_t dst, const void* gsrc) {
    uint64_t g;
    asm("cvta.to.global.u64 %0, %1;" : "=l"(g) : "l"(gsrc));
    asm volatile("cp.async.cg.shared.global [%0], [%1], 16;" :: "r"(dst), "l"(g) : "memory");
}
#define CP_COMMIT() asm volatile("cp.async.commit_group;" ::: "memory")
#define CP_WAIT0()  asm volatile("cp.async.wait_group 0;" ::: "memory")
#define CP_WAIT1()  asm volatile("cp.async.wait_group 1;" ::: "memory")

__device__ __forceinline__ void mma_f16(float* d, const uint32_t* a, uint32_t b0, uint32_t b1) {
    asm volatile(
        "mma.sync.aligned.m16n8k16.row.col.f32.f16.f16.f32 "
        "{%0,%1,%2,%3}, {%4,%5,%6,%7}, {%8,%9}, {%0,%1,%2,%3};"
        : "+f"(d[0]), "+f"(d[1]), "+f"(d[2]), "+f"(d[3])
        : "r"(a[0]), "r"(a[1]), "r"(a[2]), "r"(a[3]), "r"(b0), "r"(b1));
}

// ---------------- kernel 1: generic W -> fp16 fragment-ready layout ----------------
// Per chunk: byte = nt*512 + lane*16 + ks*8 + reg*4; chunk stride nt_total*512 bytes.
// half2 = (W[n][k], W[n][k+1]); n = nt*8 + lane/4; k = c*32 + ks*16 + (lane%4)*2 + reg*8.
__global__ void prep_frag_kernel(const float* __restrict__ W, uint32_t* __restrict__ dst,
                                 int nt_total, int n_valid) {
    const int idx = blockIdx.x * 256 + threadIdx.x;   // grid covers nt_total*2048 exactly
    const int per_chunk = nt_total * 128;
    const int c   = idx / per_chunk;
    const int rem = idx - c * per_chunk;
    const int nt  = rem >> 7;
    const int r2  = rem & 127;
    const int lane = r2 >> 2;
    const int sub  = r2 & 3;
    const int ks = sub >> 1, reg = sub & 1;
    const int n = nt * 8 + (lane >> 2);
    const int k = c * 32 + ks * 16 + (lane & 3) * 2 + reg * 8;
    float lo = 0.0f, hi = 0.0f;
    if (n < n_valid) {
        float2 w = *(const float2*)(W + (size_t)n * JJ + k);
        lo = w.x; hi = w.y;
    }
    dst[idx] = pack_h2(lo, hi);
}

// ---------------- kernel 2: enc/pred projections (fp16 mma, fp32 accum) ----------------
// Combined M = 2560 (2048 enc rows + 512 pred rows). Tile M=64 x N=128, 256 threads,
// 8 warps 2Mx4N (warp 32x32). K chunks of 32, B double-buffered via cp.async.
static constexpr int P_OFF_A    = 0;
static constexpr int P_OFF_B    = 4096;
static constexpr int P_B_STRIDE = 8192;
static constexpr int P_SMEM     = P_OFF_B + 2 * P_B_STRIDE;   // 20480

__global__ __launch_bounds__(256, 4) void proj_kernel(
    const float* __restrict__ enc, const float* __restrict__ pred,
    const float* __restrict__ b_enc, const float* __restrict__ b_pred)
{
    extern __shared__ char smem[];
    const int tid = threadIdx.x;
    const int wid = tid >> 5, lane = tid & 31;
    const int bx = blockIdx.x, by = blockIdx.y;
    const int row0 = bx * 64;
    const bool isenc = (row0 < 2048);

    const float* __restrict__ X   = isenc ? (enc + (size_t)row0 * JJ) : (pred + (size_t)(row0 - 2048) * JJ);
    float*       __restrict__ Y   = isenc ? (g_enc_s + (size_t)row0 * JJ) : (g_pred_s + (size_t)(row0 - 2048) * JJ);
    const uint32_t* __restrict__ wf = isenc ? g_wef : g_wpf;
    const float* __restrict__ bias  = isenc ? b_enc : b_pred;

    const int warp_m = wid >> 2, warp_n = wid & 3;
    const int mt0 = warp_m * 2, mt1 = warp_m * 2 + 1;

    // producer indices (one frag-lane per thread: 8 frags x 32 lanes = 256)
    const int f = tid >> 5, lf = tid & 31;
    const int pmt = f >> 1, pks = f & 1;
    const int prr = lf >> 2, pqf = lf & 3;
    const int m0 = pmt * 16 + prr, m1 = m0 + 8;
    const int cbase = pks * 16 + pqf * 2;
    const float* __restrict__ Xr0 = X + (size_t)m0 * JJ;
    const float* __restrict__ Xr1 = X + (size_t)m1 * JJ;
    char* Abuf = smem + P_OFF_A;
    const uint32_t Bsm = smem_u32(smem) + P_OFF_B;

    float acc[2][4][4];
    #pragma unroll
    for (int i = 0; i < 2; i++)
        #pragma unroll
        for (int j = 0; j < 4; j++)
            #pragma unroll
            for (int k = 0; k < 4; k++) acc[i][j][k] = 0.0f;

    // prologue: B(0)
    {
        const char* src = (const char*)(wf + ((size_t)0 * 64 + by * 16) * 128);
        #pragma unroll
        for (int ii = 0; ii < 2; ii++)
            cp_async16(Bsm + (tid + ii * 256) * 16, src + (tid + ii * 256) * 16);
        CP_COMMIT();
    }

    #pragma unroll 1
    for (int c = 0; c < NCHUNK; c++) {
        const int buf = c & 1;
        if (c + 1 < NCHUNK) {
            const char* src = (const char*)(wf + ((size_t)(c + 1) * 64 + by * 16) * 128);
            const uint32_t d = Bsm + (buf ^ 1) * P_B_STRIDE;
            #pragma unroll
            for (int ii = 0; ii < 2; ii++)
                cp_async16(d + (tid + ii * 256) * 16, src + (tid + ii * 256) * 16);
            CP_COMMIT();
        }
        // produce A(c): 4 LDG.64, 4 cvt-pack, 1 STS.128
        {
            const int c0 = c * 32 + cbase, c8 = c0 + 8;
            const float2 x0a = *(const float2*)(Xr0 + c0);
            const float2 x0b = *(const float2*)(Xr0 + c8);
            const float2 x1a = *(const float2*)(Xr1 + c0);
            const float2 x1b = *(const float2*)(Xr1 + c8);
            uint4 fr;
            fr.x = pack_h2(x0a.x, x0a.y);
            fr.y = pack_h2(x1a.x, x1a.y);
            fr.z = pack_h2(x0b.x, x0b.y);
            fr.w = pack_h2(x1b.x, x1b.y);
            *(uint4*)(Abuf + f * 512 + lf * 16) = fr;
        }
        if (c + 1 < NCHUNK) { CP_WAIT1(); } else { CP_WAIT0(); }
        __syncthreads();

        const char* Bb = smem + P_OFF_B + buf * P_B_STRIDE;
        const uint4 a00 = *(const uint4*)(Abuf + (mt0 * 2 + 0) * 512 + lane * 16);
        const uint4 a01 = *(const uint4*)(Abuf + (mt0 * 2 + 1) * 512 + lane * 16);
        const uint4 a10 = *(const uint4*)(Abuf + (mt1 * 2 + 0) * 512 + lane * 16);
        const uint4 a11 = *(const uint4*)(Abuf + (mt1 * 2 + 1) * 512 + lane * 16);
        const uint32_t A00[4] = {a00.x, a00.y, a00.z, a00.w};
        const uint32_t A01[4] = {a01.x, a01.y, a01.z, a01.w};
        const uint32_t A10[4] = {a10.x, a10.y, a10.z, a10.w};
        const uint32_t A11[4] = {a11.x, a11.y, a11.z, a11.w};
        #pragma unroll
        for (int j = 0; j < 4; j++) {
            const uint4 bq = *(const uint4*)(Bb + (warp_n * 4 + j) * 512 + lane * 16);
            mma_f16(acc[0][j], A00, bq.x, bq.y);
            mma_f16(acc[1][j], A10, bq.x, bq.y);
            mma_f16(acc[0][j], A01, bq.z, bq.w);
            mma_f16(acc[1][j], A11, bq.z, bq.w);
        }
        __syncthreads();
    }

    // epilogue
    {
        const int rr = lane >> 2, qf = lane & 3;
        #pragma unroll
        for (int i = 0; i < 2; i++) {
            #pragma unroll
            for (int half = 0; half < 2; half++) {
                const int m = warp_m * 32 + i * 16 + rr + half * 8;
                float* yrow = Y + (size_t)m * JJ;
                #pragma unroll
                for (int j = 0; j < 4; j++) {
                    const int n = by * 128 + warp_n * 32 + j * 8 + 2 * qf;
                    float2 o;
                    o.x = acc[i][j][half * 2 + 0] + bias[n];
                    o.y = acc[i][j][half * 2 + 1] + bias[n + 1];
                    *(float2*)(yrow + n) = o;
                }
            }
        }
    }
}

// ---------------- kernel 3: fused tanh-joint + vocab GEMM (fp16 mma, fp32 accum) ----------------
// Grid: 2048 CTAs = (b, t). CTA tile: M=64 (u dim) x N=320(pad) x K=512.
// 256 threads = 8 warps, warp grid 2Mx4N, warp tile 32x80. 2 CTAs/SM.
static constexpr int J_OFF_BIAS = 0;
static constexpr int J_OFF_A    = 2048;
static constexpr int J_OFF_B    = 6144;
static constexpr int J_B_STRIDE = 20480;
static constexpr int J_SMEM     = J_OFF_B + 2 * J_B_STRIDE;  // 47104

__global__ __launch_bounds__(256, 2) void joint_kernel(const float* __restrict__ b_out,
                                                       float* __restrict__ out)
{
    extern __shared__ char smem[];
    const int tid  = threadIdx.x;
    const int wid  = tid >> 5;
    const int lane = tid & 31;
    const int b    = blockIdx.x >> 8;
    const int t    = blockIdx.x & 255;

    const int warp_m = wid >> 2;      // 0..1 -> rows warp_m*32 .. +32
    const int warp_n = wid & 3;       // 0..3 -> cols warp_n*80 .. +80
    const int ntbase = warp_n * 10;
    const int mt0 = warp_m * 2, mt1 = warp_m * 2 + 1;

    float* bias_sm = (float*)(smem + J_OFF_BIAS);
    #pragma unroll
    for (int i = 0; i < 2; i++) {
        const int n = tid + i * 256;
        if (n < NP) bias_sm[n] = (n < VV) ? b_out[n] : 0.0f;
    }

    const float* __restrict__ encR  = g_enc_s + (size_t)(b * TT + t) * JJ;
    const float* __restrict__ predB = g_pred_s + (size_t)b * UU * JJ;

    // producer indices (one frag-lane per thread: 8 frags x 32 lanes = 256)
    const int f = tid >> 5, lf = tid & 31;
    const int pmt = f >> 1, pks = f & 1;
    const int prr = lf >> 2, pqf = lf & 3;
    const int u0 = pmt * 16 + prr, u1 = u0 + 8;
    const int cbase = pks * 16 + pqf * 2;
    const float* __restrict__ pR0 = predB + (size_t)u0 * JJ;
    const float* __restrict__ pR1 = predB + (size_t)u1 * JJ;
    char* Abuf = smem + J_OFF_A;
    const uint32_t Bsm = smem_u32(smem) + J_OFF_B;

    float acc[2][10][4];
    #pragma unroll
    for (int i = 0; i < 2; i++)
        #pragma unroll
        for (int j = 0; j < 10; j++)
            #pragma unroll
            for (int k = 0; k < 4; k++) acc[i][j][k] = 0.0f;

    // prologue: B(0)
    {
        const char* src = (const char*)(g_wfrag);
        #pragma unroll
        for (int ii = 0; ii < 5; ii++)
            cp_async16(Bsm + (tid + ii * 256) * 16, src + (tid + ii * 256) * 16);
        CP_COMMIT();
    }

    #pragma unroll 1
    for (int c = 0; c < NCHUNK; c++) {
        const int buf = c & 1;
        if (c + 1 < NCHUNK) {
            const char* src = (const char*)(g_wfrag + (size_t)(c + 1) * BFRAG_U32);
            const uint32_t d = Bsm + (buf ^ 1) * J_B_STRIDE;
            #pragma unroll
            for (int ii = 0; ii < 5; ii++)
                cp_async16(d + (tid + ii * 256) * 16, src + (tid + ii * 256) * 16);
            CP_COMMIT();
        }
        // produce A(c): 6 LDG.64, 8 tanh, 4 cvt-pack, 1 STS.128
        {
            const int c0 = c * 32 + cbase, c8 = c0 + 8;
            const float2 ea  = *(const float2*)(encR + c0);
            const float2 eb  = *(const float2*)(encR + c8);
            const float2 p0a = *(const float2*)(pR0 + c0);
            const float2 p0b = *(const float2*)(pR0 + c8);
            const float2 p1a = *(const float2*)(pR1 + c0);
            const float2 p1b = *(const float2*)(pR1 + c8);
            uint4 fr;
            fr.x = pack_h2(tanh_ap(ea.x + p0a.x), tanh_ap(ea.y + p0a.y));
            fr.y = pack_h2(tanh_ap(ea.x + p1a.x), tanh_ap(ea.y + p1a.y));
            fr.z = pack_h2(tanh_ap(eb.x + p0b.x), tanh_ap(eb.y + p0b.y));
            fr.w = pack_h2(tanh_ap(eb.x + p1b.x), tanh_ap(eb.y + p1b.y));
            *(uint4*)(Abuf + f * 512 + lf * 16) = fr;
        }
        if (c + 1 < NCHUNK) { CP_WAIT1(); } else { CP_WAIT0(); }
        __syncthreads();

        const char* Bb = smem + J_OFF_B + buf * J_B_STRIDE;
        const uint4 a00 = *(const uint4*)(Abuf + (mt0 * 2 + 0) * 512 + lane * 16);
        const uint4 a01 = *(const uint4*)(Abuf + (mt0 * 2 + 1) * 512 + lane * 16);
        const uint4 a10 = *(const uint4*)(Abuf + (mt1 * 2 + 0) * 512 + lane * 16);
        const uint4 a11 = *(const uint4*)(Abuf + (mt1 * 2 + 1) * 512 + lane * 16);
        const uint32_t A00[4] = {a00.x, a00.y, a00.z, a00.w};
        const uint32_t A01[4] = {a01.x, a01.y, a01.z, a01.w};
        const uint32_t A10[4] = {a10.x, a10.y, a10.z, a10.w};
        const uint32_t A11[4] = {a11.x, a11.y, a11.z, a11.w};
        #pragma unroll
        for (int nt = 0; nt < 10; nt++) {
            const uint4 bq = *(const uint4*)(Bb + (ntbase + nt) * 512 + lane * 16);
            mma_f16(acc[0][nt], A00, bq.x, bq.y);   // kstep 0
            mma_f16(acc[1][nt], A10, bq.x, bq.y);
            mma_f16(acc[0][nt], A01, bq.z, bq.w);   // kstep 1
            mma_f16(acc[1][nt], A11, bq.z, bq.w);
        }
        __syncthreads();
    }

    // epilogue: bias add + guarded float2 stores
    {
        const int rr = lane >> 2, qf = lane & 3;
        #pragma unroll
        for (int i = 0; i < 2; i++) {
            #pragma unroll
            for (int half = 0; half < 2; half++) {
                const int u = warp_m * 32 + i * 16 + rr + half * 8;
                float* orow = out + (size_t)((b * TT + t) * UU + u) * VV;
                #pragma unroll
                for (int nt = 0; nt < 10; nt++) {
                    const int n0 = warp_n * 80 + nt * 8 + 2 * qf;
                    if (n0 < VV) {
                        float2 o;
                        o.x = acc[i][nt][half * 2 + 0] + bias_sm[n0];
                        o.y = acc[i][nt][half * 2 + 1] + bias_sm[n0 + 1];
                        *(float2*)(orow + n0) = o;
                    }
                }
            }
        }
    }
}

// ---------------- launch ----------------
extern "C" void kernel_launch(void* const* d_in, const int* in_sizes, int n_in,
                              void* d_out, int out_size) {
    const float* enc    = (const float*)d_in[0];
    const float* pred   = (const float*)d_in[1];
    const float* W_enc  = (const float*)d_in[2];
    const float* b_enc  = (const float*)d_in[3];
    const float* W_pred = (const float*)d_in[4];
    const float* b_pred = (const float*)d_in[5];
    const float* W_out  = (const float*)d_in[6];
    const float* b_out  = (const float*)d_in[7];
    float* out = (float*)d_out;

    uint32_t* wfrag_p; uint32_t* wef_p; uint32_t* wpf_p;
    cudaGetSymbolAddress((void**)&wfrag_p, g_wfrag);
    cudaGetSymbolAddress((void**)&wef_p,  g_wef);
    cudaGetSymbolAddress((void**)&wpf_p,  g_wpf);

    cudaFuncSetAttribute(joint_kernel, cudaFuncAttributeMaxDynamicSharedMemorySize, J_SMEM);
    cudaFuncSetAttribute(proj_kernel,  cudaFuncAttributeMaxDynamicSharedMemorySize, P_SMEM);

    prep_frag_kernel<<<(40 * 2048) / 256, 256>>>(W_out,  wfrag_p, 40, VV);
    prep_frag_kernel<<<(64 * 2048) / 256, 256>>>(W_enc,  wef_p,   64, 512);
    prep_frag_kernel<<<(64 * 2048) / 256, 256>>>(W_pred, wpf_p,   64, 512);
    proj_kernel<<<dim3(40, 4), 256, P_SMEM>>>(enc, pred, b_enc, b_pred);
    joint_kernel<<<BB * TT, 256, J_SMEM>>>(b_out, out);
}

// round 8
// speedup vs baseline: 2.4338x; 1.0294x over previous
#include <cuda_runtime.h>
#include <cuda_fp16.h>
#include <cstdint>

// ---------------- problem constants ----------------
#define BB 8
#define TT 256
#define UU 64
#define JJ 512          // K dim
#define VV 300          // vocab
#define NP 304          // padded vocab (mult of 8)
#define NTT 38          // joint n-tiles (NP/8)
#define NCHUNK 16       // K chunks of 32
#define BFRAG_U32 4864  // joint B frag u32 per chunk: 38 nt * 128

// ---------------- scratch (device globals; no allocs allowed) ----------------
__device__ __align__(16) float    g_enc_s[BB * TT * JJ];         // 4 MB   (enc projection out)
__device__ __align__(16) float    g_pred_s[BB * UU * JJ];        // 1 MB   (pred projection out)
__device__ __align__(16) uint32_t g_wfrag[NCHUNK * BFRAG_U32];   // 304 KB (W_out fp16 frags)
__device__ __align__(16) uint32_t g_wef[NCHUNK * 64 * 128];      // 512 KB (W_enc fp16 frags)
__device__ __align__(16) uint32_t g_wpf[NCHUNK * 64 * 128];      // 512 KB (W_pred fp16 frags)

// ---------------- helpers ----------------
__device__ __forceinline__ uint32_t smem_u32(const void* p) {
    uint32_t a;
    asm("{ .reg .u64 t; cvta.to.shared.u64 t, %1; cvt.u32.u64 %0, t; }" : "=r"(a) : "l"(p));
    return a;
}

__device__ __forceinline__ float tanh_ap(float x) {
    float y;
    asm("tanh.approx.f32 %0, %1;" : "=f"(y) : "f"(x));
    return y;
}

__device__ __forceinline__ uint32_t pack_h2(float lo, float hi) {
    half2 h = __floats2half2_rn(lo, hi);
    return *(uint32_t*)&h;
}

__device__ __forceinline__ void cp_async16(uint32_t dst, const void* gsrc) {
    uint64_t g;
    asm("cvta.to.global.u64 %0, %1;" : "=l"(g) : "l"(gsrc));
    asm volatile("cp.async.cg.shared.global [%0], [%1], 16;" :: "r"(dst), "l"(g) : "memory");
}
#define CP_COMMIT() asm volatile("cp.async.commit_group;" ::: "memory")
#define CP_WAIT0()  asm volatile("cp.async.wait_group 0;" ::: "memory")
#define CP_WAIT1()  asm volatile("cp.async.wait_group 1;" ::: "memory")

__device__ __forceinline__ void mma_f16(float* d, const uint32_t* a, uint32_t b0, uint32_t b1) {
    asm volatile(
        "mma.sync.aligned.m16n8k16.row.col.f32.f16.f16.f32 "
        "{%0,%1,%2,%3}, {%4,%5,%6,%7}, {%8,%9}, {%0,%1,%2,%3};"
        : "+f"(d[0]), "+f"(d[1]), "+f"(d[2]), "+f"(d[3])
        : "r"(a[0]), "r"(a[1]), "r"(a[2]), "r"(a[3]), "r"(b0), "r"(b1));
}

// ---------------- kernel 1: all weights -> fp16 fragment-ready layout (one launch) ----------------
// Per chunk: byte = nt*512 + lane*16 + ks*8 + reg*4; chunk stride nt_total*512 bytes.
// half2 = (W[n][k], W[n][k+1]); n = nt*8 + lane/4; k = c*32 + ks*16 + (lane%4)*2 + reg*8.
__global__ void prep_frag_kernel(const float* __restrict__ W_out,
                                 const float* __restrict__ W_enc,
                                 const float* __restrict__ W_pred) {
    const int z = blockIdx.y;
    const float* W; uint32_t* dst; int nt_total, n_valid;
    if (z == 0)      { W = W_out;  dst = g_wfrag; nt_total = NTT; n_valid = VV; }
    else if (z == 1) { W = W_enc;  dst = g_wef;   nt_total = 64;  n_valid = 512; }
    else             { W = W_pred; dst = g_wpf;   nt_total = 64;  n_valid = 512; }

    const int idx = blockIdx.x * 256 + threadIdx.x;
    const int per_chunk = nt_total * 128;
    if (idx >= NCHUNK * per_chunk) return;
    const int c   = idx / per_chunk;
    const int rem = idx - c * per_chunk;
    const int nt  = rem >> 7;
    const int r2  = rem & 127;
    const int lane = r2 >> 2;
    const int sub  = r2 & 3;
    const int ks = sub >> 1, reg = sub & 1;
    const int n = nt * 8 + (lane >> 2);
    const int k = c * 32 + ks * 16 + (lane & 3) * 2 + reg * 8;
    float lo = 0.0f, hi = 0.0f;
    if (n < n_valid) {
        float2 w = *(const float2*)(W + (size_t)n * JJ + k);
        lo = w.x; hi = w.y;
    }
    dst[idx] = pack_h2(lo, hi);
}

// ---------------- kernel 2: enc/pred projections (fp16 mma, fp32 accum) ----------------
// Combined M = 2560 (2048 enc + 512 pred). Tile M=32 x N=128, 256 threads,
// 8 warps each 32x16 (2 n-tiles). 320 CTAs. K chunks of 32, B double-buffered cp.async.
static constexpr int P_OFF_A    = 0;       // 4 frags x 512B = 2KB
static constexpr int P_OFF_B    = 2048;
static constexpr int P_B_STRIDE = 8192;    // 16 nt x 512B
static constexpr int P_SMEM     = P_OFF_B + 2 * P_B_STRIDE;   // 18432

__global__ __launch_bounds__(256, 4) void proj_kernel(
    const float* __restrict__ enc, const float* __restrict__ pred,
    const float* __restrict__ b_enc, const float* __restrict__ b_pred)
{
    extern __shared__ char smem[];
    const int tid = threadIdx.x;
    const int wid = tid >> 5, lane = tid & 31;
    const int bx = blockIdx.x, by = blockIdx.y;
    const int row0 = bx * 32;
    const bool isenc = (row0 < 2048);

    const float* __restrict__ X   = isenc ? (enc + (size_t)row0 * JJ) : (pred + (size_t)(row0 - 2048) * JJ);
    float*       __restrict__ Y   = isenc ? (g_enc_s + (size_t)row0 * JJ) : (g_pred_s + (size_t)(row0 - 2048) * JJ);
    const uint32_t* __restrict__ wf = isenc ? g_wef : g_wpf;
    const float* __restrict__ bias  = isenc ? b_enc : b_pred;

    // producer indices (threads 0..127: one frag-lane each; 4 frags x 32 lanes)
    const int f = tid >> 5, lf = tid & 31;
    const int pmt = f >> 1, pks = f & 1;
    const int prr = lf >> 2, pqf = lf & 3;
    const int m0 = pmt * 16 + prr, m1 = m0 + 8;
    const int cbase = pks * 16 + pqf * 2;
    const float* __restrict__ Xr0 = X + (size_t)m0 * JJ;
    const float* __restrict__ Xr1 = X + (size_t)m1 * JJ;
    char* Abuf = smem + P_OFF_A;
    const uint32_t Bsm = smem_u32(smem) + P_OFF_B;

    float acc[2][2][4];
    #pragma unroll
    for (int i = 0; i < 2; i++)
        #pragma unroll
        for (int j = 0; j < 2; j++)
            #pragma unroll
            for (int k = 0; k < 4; k++) acc[i][j][k] = 0.0f;

    // prologue: B(0)
    {
        const char* src = (const char*)(wf + ((size_t)0 * 64 + by * 16) * 128);
        #pragma unroll
        for (int ii = 0; ii < 2; ii++)
            cp_async16(Bsm + (tid + ii * 256) * 16, src + (tid + ii * 256) * 16);
        CP_COMMIT();
    }

    #pragma unroll 1
    for (int c = 0; c < NCHUNK; c++) {
        const int buf = c & 1;
        if (c + 1 < NCHUNK) {
            const char* src = (const char*)(wf + ((size_t)(c + 1) * 64 + by * 16) * 128);
            const uint32_t d = Bsm + (buf ^ 1) * P_B_STRIDE;
            #pragma unroll
            for (int ii = 0; ii < 2; ii++)
                cp_async16(d + (tid + ii * 256) * 16, src + (tid + ii * 256) * 16);
            CP_COMMIT();
        }
        if (tid < 128) {   // produce A(c): 4 LDG.64, 4 cvt-pack, 1 STS.128
            const int c0 = c * 32 + cbase, c8 = c0 + 8;
            const float2 x0a = *(const float2*)(Xr0 + c0);
            const float2 x0b = *(const float2*)(Xr0 + c8);
            const float2 x1a = *(const float2*)(Xr1 + c0);
            const float2 x1b = *(const float2*)(Xr1 + c8);
            uint4 fr;
            fr.x = pack_h2(x0a.x, x0a.y);
            fr.y = pack_h2(x1a.x, x1a.y);
            fr.z = pack_h2(x0b.x, x0b.y);
            fr.w = pack_h2(x1b.x, x1b.y);
            *(uint4*)(Abuf + f * 512 + lf * 16) = fr;
        }
        if (c + 1 < NCHUNK) { CP_WAIT1(); } else { CP_WAIT0(); }
        __syncthreads();

        const char* Bb = smem + P_OFF_B + buf * P_B_STRIDE;
        const uint4 a00 = *(const uint4*)(Abuf + 0 * 512 + lane * 16);
        const uint4 a01 = *(const uint4*)(Abuf + 1 * 512 + lane * 16);
        const uint4 a10 = *(const uint4*)(Abuf + 2 * 512 + lane * 16);
        const uint4 a11 = *(const uint4*)(Abuf + 3 * 512 + lane * 16);
        const uint32_t A00[4] = {a00.x, a00.y, a00.z, a00.w};
        const uint32_t A01[4] = {a01.x, a01.y, a01.z, a01.w};
        const uint32_t A10[4] = {a10.x, a10.y, a10.z, a10.w};
        const uint32_t A11[4] = {a11.x, a11.y, a11.z, a11.w};
        #pragma unroll
        for (int j = 0; j < 2; j++) {
            const uint4 bq = *(const uint4*)(Bb + (wid * 2 + j) * 512 + lane * 16);
            mma_f16(acc[0][j], A00, bq.x, bq.y);
            mma_f16(acc[1][j], A10, bq.x, bq.y);
            mma_f16(acc[0][j], A01, bq.z, bq.w);
            mma_f16(acc[1][j], A11, bq.z, bq.w);
        }
        __syncthreads();
    }

    // epilogue
    {
        const int rr = lane >> 2, qf = lane & 3;
        #pragma unroll
        for (int i = 0; i < 2; i++) {
            #pragma unroll
            for (int half = 0; half < 2; half++) {
                const int m = i * 16 + rr + half * 8;
                float* yrow = Y + (size_t)m * JJ;
                #pragma unroll
                for (int j = 0; j < 2; j++) {
                    const int n = by * 128 + wid * 16 + j * 8 + 2 * qf;
                    float2 o;
                    o.x = acc[i][j][half * 2 + 0] + bias[n];
                    o.y = acc[i][j][half * 2 + 1] + bias[n + 1];
                    *(float2*)(yrow + n) = o;
                }
            }
        }
    }
}

// ---------------- kernel 3: fused tanh-joint + vocab GEMM (fp16 mma, fp32 accum) ----------------
// Grid: 2048 CTAs = (b, t). CTA tile: M=64 (u dim) x N=304 x K=512.
// 256 threads = 8 warps, warp grid 2Mx4N; warps n0-2: 80 cols, warp n3: 64 cols. 2 CTAs/SM.
static constexpr int J_OFF_BIAS = 0;       // 304 x 4 = 1216 B
static constexpr int J_OFF_A    = 2048;    // 8 frags x 512B = 4KB
static constexpr int J_OFF_B    = 6144;
static constexpr int J_B_STRIDE = 19456;   // 38 nt x 512B
static constexpr int J_SMEM     = J_OFF_B + 2 * J_B_STRIDE;  // 45056

__global__ __launch_bounds__(256, 2) void joint_kernel(const float* __restrict__ b_out,
                                                       float* __restrict__ out)
{
    extern __shared__ char smem[];
    const int tid  = threadIdx.x;
    const int wid  = tid >> 5;
    const int lane = tid & 31;
    const int b    = blockIdx.x >> 8;
    const int t    = blockIdx.x & 255;

    const int warp_m = wid >> 2;      // 0..1 -> rows warp_m*32 .. +32
    const int warp_n = wid & 3;       // 0..3
    const int ntbase = warp_n * 10;
    const int ntcnt  = (warp_n == 3) ? 8 : 10;   // 38 total
    const int mt0 = warp_m * 2, mt1 = warp_m * 2 + 1;

    float* bias_sm = (float*)(smem + J_OFF_BIAS);
    #pragma unroll
    for (int i = 0; i < 2; i++) {
        const int n = tid + i * 256;
        if (n < NP) bias_sm[n] = (n < VV) ? b_out[n] : 0.0f;
    }

    const float* __restrict__ encR  = g_enc_s + (size_t)(b * TT + t) * JJ;
    const float* __restrict__ predB = g_pred_s + (size_t)b * UU * JJ;

    // producer indices (one frag-lane per thread: 8 frags x 32 lanes = 256)
    const int f = tid >> 5, lf = tid & 31;
    const int pmt = f >> 1, pks = f & 1;
    const int prr = lf >> 2, pqf = lf & 3;
    const int u0 = pmt * 16 + prr, u1 = u0 + 8;
    const int cbase = pks * 16 + pqf * 2;
    const float* __restrict__ pR0 = predB + (size_t)u0 * JJ;
    const float* __restrict__ pR1 = predB + (size_t)u1 * JJ;
    char* Abuf = smem + J_OFF_A;
    const uint32_t Bsm = smem_u32(smem) + J_OFF_B;

    float acc[2][10][4];
    #pragma unroll
    for (int i = 0; i < 2; i++)
        #pragma unroll
        for (int j = 0; j < 10; j++)
            #pragma unroll
            for (int k = 0; k < 4; k++) acc[i][j][k] = 0.0f;

    // prologue: B(0)  (1216 uint4 per chunk)
    {
        const char* src = (const char*)(g_wfrag);
        #pragma unroll
        for (int ii = 0; ii < 5; ii++) {
            const int w = tid + ii * 256;
            if (w < 1216) cp_async16(Bsm + w * 16, src + w * 16);
        }
        CP_COMMIT();
    }

    #pragma unroll 1
    for (int c = 0; c < NCHUNK; c++) {
        const int buf = c & 1;
        if (c + 1 < NCHUNK) {
            const char* src = (const char*)(g_wfrag + (size_t)(c + 1) * BFRAG_U32);
            const uint32_t d = Bsm + (buf ^ 1) * J_B_STRIDE;
            #pragma unroll
            for (int ii = 0; ii < 5; ii++) {
                const int w = tid + ii * 256;
                if (w < 1216) cp_async16(d + w * 16, src + w * 16);
            }
            CP_COMMIT();
        }
        // produce A(c): 6 LDG.64, 8 tanh, 4 cvt-pack, 1 STS.128
        {
            const int c0 = c * 32 + cbase, c8 = c0 + 8;
            const float2 ea  = *(const float2*)(encR + c0);
            const float2 eb  = *(const float2*)(encR + c8);
            const float2 p0a = *(const float2*)(pR0 + c0);
            const float2 p0b = *(const float2*)(pR0 + c8);
            const float2 p1a = *(const float2*)(pR1 + c0);
            const float2 p1b = *(const float2*)(pR1 + c8);
            uint4 fr;
            fr.x = pack_h2(tanh_ap(ea.x + p0a.x), tanh_ap(ea.y + p0a.y));
            fr.y = pack_h2(tanh_ap(ea.x + p1a.x), tanh_ap(ea.y + p1a.y));
            fr.z = pack_h2(tanh_ap(eb.x + p0b.x), tanh_ap(eb.y + p0b.y));
            fr.w = pack_h2(tanh_ap(eb.x + p1b.x), tanh_ap(eb.y + p1b.y));
            *(uint4*)(Abuf + f * 512 + lf * 16) = fr;
        }
        if (c + 1 < NCHUNK) { CP_WAIT1(); } else { CP_WAIT0(); }
        __syncthreads();

        const char* Bb = smem + J_OFF_B + buf * J_B_STRIDE;
        const uint4 a00 = *(const uint4*)(Abuf + (mt0 * 2 + 0) * 512 + lane * 16);
        const uint4 a01 = *(const uint4*)(Abuf + (mt0 * 2 + 1) * 512 + lane * 16);
        const uint4 a10 = *(const uint4*)(Abuf + (mt1 * 2 + 0) * 512 + lane * 16);
        const uint4 a11 = *(const uint4*)(Abuf + (mt1 * 2 + 1) * 512 + lane * 16);
        const uint32_t A00[4] = {a00.x, a00.y, a00.z, a00.w};
        const uint32_t A01[4] = {a01.x, a01.y, a01.z, a01.w};
        const uint32_t A10[4] = {a10.x, a10.y, a10.z, a10.w};
        const uint32_t A11[4] = {a11.x, a11.y, a11.z, a11.w};
        #pragma unroll
        for (int nt = 0; nt < 10; nt++) {
            if (nt < ntcnt) {
                const uint4 bq = *(const uint4*)(Bb + (ntbase + nt) * 512 + lane * 16);
                mma_f16(acc[0][nt], A00, bq.x, bq.y);   // kstep 0
                mma_f16(acc[1][nt], A10, bq.x, bq.y);
                mma_f16(acc[0][nt], A01, bq.z, bq.w);   // kstep 1
                mma_f16(acc[1][nt], A11, bq.z, bq.w);
            }
        }
        __syncthreads();
    }

    // epilogue: bias add + guarded float2 stores
    {
        const int rr = lane >> 2, qf = lane & 3;
        #pragma unroll
        for (int i = 0; i < 2; i++) {
            #pragma unroll
            for (int half = 0; half < 2; half++) {
                const int u = warp_m * 32 + i * 16 + rr + half * 8;
                float* orow = out + (size_t)((b * TT + t) * UU + u) * VV;
                #pragma unroll
                for (int nt = 0; nt < 10; nt++) {
                    const int n0 = (ntbase + nt) * 8 + 2 * qf;
                    if (nt < ntcnt && n0 < VV) {
                        float2 o;
                        o.x = acc[i][nt][half * 2 + 0] + bias_sm[n0];
                        o.y = acc[i][nt][half * 2 + 1] + bias_sm[n0 + 1];
                        *(float2*)(orow + n0) = o;
                    }
                }
            }
        }
    }
}

// ---------------- launch ----------------
extern "C" void kernel_launch(void* const* d_in, const int* in_sizes, int n_in,
                              void* d_out, int out_size) {
    const float* enc    = (const float*)d_in[0];
    const float* pred   = (const float*)d_in[1];
    const float* W_enc  = (const float*)d_in[2];
    const float* b_enc  = (const float*)d_in[3];
    const float* W_pred = (const float*)d_in[4];
    const float* b_pred = (const float*)d_in[5];
    const float* W_out  = (const float*)d_in[6];
    const float* b_out  = (const float*)d_in[7];
    float* out = (float*)d_out;

    cudaFuncSetAttribute(joint_kernel, cudaFuncAttributeMaxDynamicSharedMemorySize, J_SMEM);
    cudaFuncSetAttribute(proj_kernel,  cudaFuncAttributeMaxDynamicSharedMemorySize, P_SMEM);

    prep_frag_kernel<<<dim3(512, 3), 256>>>(W_out, W_enc, W_pred);
    proj_kernel<<<dim3(80, 4), 256, P_SMEM>>>(enc, pred, b_enc, b_pred);
    joint_kernel<<<BB * TT, 256, J_SMEM>>>(b_out, out);
}